// round 9
// baseline (speedup 1.0000x reference)
#include <cuda_runtime.h>
#include <cuda_fp16.h>
#include <math.h>
#include <stdint.h>

#define N_NODES 4096
#define N_EDGES 16384
#define D       64
#define BG      16
#define SLOPE   0.01f
#define NCHUNK  65              // 64 kk chunks + 1 bias chunk

// ---------------- device scratch ----------------
__device__ __half g_Bt[NCHUNK * 4096];           // [kk][f][d] transposed We2 + bias chunk
__device__ __half g_he_h[N_EDGES * D];
__device__ __half g_h_h[N_NODES * D];            // fp16 mirror of h
__device__ float g_h[N_NODES * D];
__device__ float g_agg[N_NODES * D];
__device__ float g_deg[N_NODES];
__device__ float g_Wi4[D * D * 4];
__device__ float g_Wh4[D * D * 4];
__device__ float g_q[D];
__device__ float g_e[N_NODES];
__device__ float g_a[N_NODES];
__device__ float g_emax[BG];
__device__ float g_asum[BG];
__device__ float g_rpool[BG * D];

__device__ __forceinline__ float lrelu(float x) { return x >= 0.f ? x : SLOPE * x; }
__device__ __forceinline__ float sigm(float x)  { return 1.f / (1.f + expf(-x)); }

__device__ __forceinline__ void atomicMaxF(float* addr, float v) {
    int* ai = (int*)addr;
    int old = *ai;
    while (__int_as_float(old) < v) {
        int assumed = old;
        old = atomicCAS(ai, assumed, __float_as_int(v));
        if (old == assumed) break;
    }
}

__device__ __forceinline__ void mma16816(float c[4],
                                         uint32_t a0, uint32_t a1, uint32_t a2, uint32_t a3,
                                         uint32_t b0, uint32_t b1) {
    asm volatile(
        "mma.sync.aligned.m16n8k16.row.col.f32.f16.f16.f32 "
        "{%0,%1,%2,%3}, {%4,%5,%6,%7}, {%8,%9}, {%0,%1,%2,%3};"
        : "+f"(c[0]), "+f"(c[1]), "+f"(c[2]), "+f"(c[3])
        : "r"(a0), "r"(a1), "r"(a2), "r"(a3), "r"(b0), "r"(b1));
}

__device__ __forceinline__ void ldsm_x4(uint32_t& r0, uint32_t& r1,
                                        uint32_t& r2, uint32_t& r3,
                                        const void* smem_ptr) {
    uint32_t addr;
    asm("{ .reg .u64 t; cvta.to.shared.u64 t, %1; cvt.u32.u64 %0, t; }"
        : "=r"(addr) : "l"(smem_ptr));
    asm volatile("ldmatrix.sync.aligned.m8n8.x4.shared.b16 {%0,%1,%2,%3}, [%4];"
                 : "=r"(r0), "=r"(r1), "=r"(r2), "=r"(r3) : "r"(addr));
}

__device__ __forceinline__ uint32_t smem_u32(const void* p) {
    uint32_t a;
    asm("{ .reg .u64 t; cvta.to.shared.u64 t, %1; cvt.u32.u64 %0, t; }"
        : "=r"(a) : "l"(p));
    return a;
}

#define CPA16(dst_u32, src_ptr) \
    asm volatile("cp.async.cg.shared.global [%0], [%1], 16;" :: "r"(dst_u32), "l"(src_ptr))
#define CPA_COMMIT() asm volatile("cp.async.commit_group;" ::: "memory")
#define CPA_WAIT1()  asm volatile("cp.async.wait_group 1;" ::: "memory")

__device__ __forceinline__ uint32_t hmul2u(uint32_t a, uint32_t b) {
    __half2 r = __hmul2(*(__half2*)&a, *(__half2*)&b);
    return *(uint32_t*)&r;
}

// ---------------- prep kernels ----------------

// h0 = lrelu(x @ W0 + b0); also zero agg + deg
__global__ void k_node_init(const float* __restrict__ x,
                            const float* __restrict__ W0,
                            const float* __restrict__ b0) {
    int idx = blockIdx.x * blockDim.x + threadIdx.x;
    if (idx >= N_NODES * D) return;
    int n = idx >> 6, f = idx & 63;
    float acc = b0[f];
    acc += x[n * 3 + 0] * W0[0 * D + f];
    acc += x[n * 3 + 1] * W0[1 * D + f];
    acc += x[n * 3 + 2] * W0[2 * D + f];
    float v = lrelu(acc);
    g_h[idx] = v;
    g_h_h[idx] = __float2half(v);
    g_agg[idx] = 0.f;
    if (f == 0) g_deg[n] = 0.f;
}

__global__ void k_edge_init(const float* __restrict__ ea,
                            const float* __restrict__ We1,
                            const float* __restrict__ be1,
                            const int* __restrict__ ei) {
    int idx = blockIdx.x * blockDim.x + threadIdx.x;
    if (idx >= N_EDGES * D) return;
    int e = idx >> 6, f = idx & 63;
    float acc = be1[f];
    acc += ea[e * 4 + 0] * We1[0 * D + f];
    acc += ea[e * 4 + 1] * We1[1 * D + f];
    acc += ea[e * 4 + 2] * We1[2 * D + f];
    acc += ea[e * 4 + 3] * We1[3 * D + f];
    g_he_h[idx] = __float2half(lrelu(acc));
    if (f == 0) {
        int dst = ei[N_EDGES + e];
        atomicAdd(&g_deg[dst], 1.f);
    }
}

// g_Bt[kk][f][d] = We2[kk][d*64+f]  (kk<64), be2[d*64+f] (kk==64)
__global__ void k_prep_bt(const float* __restrict__ We2,
                          const float* __restrict__ be2) {
    int idx = blockIdx.x * blockDim.x + threadIdx.x;
    if (idx >= NCHUNK * 4096) return;
    int kk = idx >> 12, r = idx & 4095;
    int f = r >> 6, d = r & 63;
    float v = (kk < 64) ? We2[kk * 4096 + d * 64 + f] : be2[d * 64 + f];
    g_Bt[kk * 4096 + f * 64 + d] = __float2half(v);
}

__global__ void k_prep_gru(const float* __restrict__ Wih,
                           const float* __restrict__ Whh) {
    int idx = blockIdx.x * blockDim.x + threadIdx.x;
    if (idx >= D * D * 4) return;
    int gg = idx & 3, f = (idx >> 2) & 63, k = idx >> 8;
    float vi = 0.f, vh = 0.f;
    if (gg < 3) {
        vi = Wih[(gg * 64 + f) * 64 + k];
        vh = Whh[(gg * 64 + f) * 64 + k];
    }
    g_Wi4[idx] = vi;
    g_Wh4[idx] = vh;
}

// ---------------- fused edge GEMM + scatter ----------------
// msg[e,f] = sum_{kk,d} he[e,kk] * h[src,d] * We2[kk, d*64+f]  (+ bias chunk kk=64)
// 64 edges/block, 128 threads, 4 warps in 2m x 2n grid; each warp m32 x n32.
// B fragments per chunk loaded once per warp, reused across both m16 sub-tiles.
__global__ void __launch_bounds__(128) k_msg_fused(const int* __restrict__ ei) {
    __shared__ __half sHe[64][72];      // he tile + bias col 64 = 1.0
    __shared__ __half sHs[64][72];      // gathered h[src]
    __shared__ __half sB[3][64][72];    // streamed B chunks, 3-deep ring
    __shared__ int sDst[64];
    __shared__ int sSrc[64];

    int ebase = blockIdx.x * 64;
    int tid = threadIdx.x;

    if (tid < 64) {
        sSrc[tid] = ei[ebase + tid];
        sDst[tid] = ei[N_EDGES + ebase + tid];
    }
    __syncthreads();

#pragma unroll
    for (int i = 0; i < 4; i++) {
        int u = tid * 4 + i;              // 512 uint4 = 64 rows x 8
        int row = u >> 3, ch = u & 7;
        *(uint4*)&sHe[row][ch * 8] = *(const uint4*)&g_he_h[(ebase + row) * D + ch * 8];
        *(uint4*)&sHs[row][ch * 8] = *(const uint4*)&g_h_h[sSrc[row] * D + ch * 8];
    }
    if (tid < 64) sHe[tid][64] = __float2half(1.0f);

    // preload chunks 0,1 (one commit group each)
#pragma unroll
    for (int p = 0; p < 2; p++) {
#pragma unroll
        for (int i = 0; i < 4; i++) {
            int u = tid * 4 + i;
            int row = u >> 3, ch = u & 7;
            CPA16(smem_u32(&sB[p][row][ch * 8]),
                  (const char*)(g_Bt + (size_t)p * 4096 + row * 64 + ch * 8));
        }
        CPA_COMMIT();
    }
    __syncthreads();   // sHe/sHs visible

    int warp = tid >> 5, lane = tid & 31;
    int wm = warp & 1, wn = warp >> 1;
    int g = lane >> 2, tig = lane & 3;
    int a_row = (lane & 7) + ((lane & 8) ? 8 : 0);
    int a_col8 = (lane & 16) ? 8 : 0;
    int b_row = (lane & 7) + ((lane & 16) ? 8 : 0);
    int b_col8 = (lane & 8) ? 8 : 0;

    // loop-invariant h[src] fragments: 2 m16 tiles x 4 k-steps
    uint32_t hs[2][4][4];
#pragma unroll
    for (int t = 0; t < 2; t++)
#pragma unroll
        for (int s = 0; s < 4; s++)
            ldsm_x4(hs[t][s][0], hs[t][s][1], hs[t][s][2], hs[t][s][3],
                    &sHs[wm * 32 + t * 16 + a_row][s * 16 + a_col8]);

    float c[2][4][4];
#pragma unroll
    for (int t = 0; t < 2; t++)
#pragma unroll
        for (int j = 0; j < 4; j++)
            c[t][j][0] = c[t][j][1] = c[t][j][2] = c[t][j][3] = 0.f;

    for (int kk = 0; kk < NCHUNK; kk++) {
        int cur = kk % 3;
        CPA_WAIT1();       // chunk kk's group drained (1 newer may remain)
        __syncthreads();   // chunk kk visible to all warps; compute kk-1 done
        if (kk + 2 < NCHUNK) {
            int nb = (kk + 2) % 3;       // slot (kk-1)%3: compute kk-1 finished
#pragma unroll
            for (int i = 0; i < 4; i++) {
                int u = tid * 4 + i;
                int row = u >> 3, ch = u & 7;
                CPA16(smem_u32(&sB[nb][row][ch * 8]),
                      (const char*)(g_Bt + (size_t)(kk + 2) * 4096 + row * 64 + ch * 8));
            }
        }
        CPA_COMMIT();      // uniform group count per iteration

        // per-m-tile he broadcast values
        uint32_t heu[2][2];
#pragma unroll
        for (int t = 0; t < 2; t++) {
            __half2 h0 = __half2half2(sHe[wm * 32 + t * 16 + g][kk]);
            __half2 h1 = __half2half2(sHe[wm * 32 + t * 16 + g + 8][kk]);
            heu[t][0] = *(uint32_t*)&h0;
            heu[t][1] = *(uint32_t*)&h1;
        }

#pragma unroll
        for (int s = 0; s < 4; s++) {
            uint32_t bf[2][4];
#pragma unroll
            for (int jp = 0; jp < 2; jp++)
                ldsm_x4(bf[jp][0], bf[jp][1], bf[jp][2], bf[jp][3],
                        &sB[cur][wn * 32 + jp * 16 + b_row][s * 16 + b_col8]);
#pragma unroll
            for (int t = 0; t < 2; t++) {
                uint32_t a0 = hmul2u(heu[t][0], hs[t][s][0]);
                uint32_t a1 = hmul2u(heu[t][1], hs[t][s][1]);
                uint32_t a2 = hmul2u(heu[t][0], hs[t][s][2]);
                uint32_t a3 = hmul2u(heu[t][1], hs[t][s][3]);
#pragma unroll
                for (int jp = 0; jp < 2; jp++) {
                    mma16816(c[t][2 * jp],     a0, a1, a2, a3, bf[jp][0], bf[jp][1]);
                    mma16816(c[t][2 * jp + 1], a0, a1, a2, a3, bf[jp][2], bf[jp][3]);
                }
            }
        }
    }

    // scatter to agg
#pragma unroll
    for (int t = 0; t < 2; t++) {
        int e0 = wm * 32 + t * 16 + g;
        int e1 = e0 + 8;
        int dst0 = sDst[e0], dst1 = sDst[e1];
#pragma unroll
        for (int j = 0; j < 4; j++) {
            int col = wn * 32 + j * 8 + 2 * tig;
            atomicAdd(&g_agg[dst0 * D + col],     c[t][j][0]);
            atomicAdd(&g_agg[dst0 * D + col + 1], c[t][j][1]);
            atomicAdd(&g_agg[dst1 * D + col],     c[t][j][2]);
            atomicAdd(&g_agg[dst1 * D + col + 1], c[t][j][3]);
        }
    }
}

// ---------------- node update ----------------
__global__ void k_node_update(const float* __restrict__ root,
                              const float* __restrict__ conv_b,
                              const float* __restrict__ bih,
                              const float* __restrict__ bhh) {
    __shared__ float sh[16][D];
    __shared__ float sm[16][D];
    __shared__ float sroot[D][D];
    int nb = blockIdx.x * 16;
    int tid = threadIdx.x;
    int f = tid & 63, ng = tid >> 6;

#pragma unroll
    for (int i = 0; i < 4; i++) {
        int ln = ng + 4 * i;
        sh[ln][f] = g_h[(nb + ln) * D + f];
    }
#pragma unroll
    for (int i = 0; i < 16; i++) {
        int idx = tid + i * 256;
        sroot[idx >> 6][idx & 63] = root[idx];
    }
    __syncthreads();

    float cb = conv_b[f];
#pragma unroll
    for (int i = 0; i < 4; i++) {
        int ln = ng + 4 * i;
        int n = nb + ln;
        float invd = 1.f / fmaxf(g_deg[n], 1.f);
        float acc = g_agg[n * D + f] * invd + cb;
        g_agg[n * D + f] = 0.f;
#pragma unroll 8
        for (int d = 0; d < D; d++) acc += sh[ln][d] * sroot[d][f];
        sm[ln][f] = lrelu(acc);
    }
    __syncthreads();

    float gir[4], giz[4], gin[4], ghr[4], ghz[4], ghn[4];
    float bir = bih[f], biz = bih[D + f], bin = bih[2 * D + f];
    float bhr = bhh[f], bhz = bhh[D + f], bhn = bhh[2 * D + f];
#pragma unroll
    for (int i = 0; i < 4; i++) {
        gir[i] = bir; giz[i] = biz; gin[i] = bin;
        ghr[i] = bhr; ghz[i] = bhz; ghn[i] = bhn;
    }

#pragma unroll 4
    for (int k = 0; k < D; k++) {
        float4 wi = *(const float4*)&g_Wi4[(k * D + f) * 4];
        float4 wh = *(const float4*)&g_Wh4[(k * D + f) * 4];
#pragma unroll
        for (int i = 0; i < 4; i++) {
            int ln = ng + 4 * i;
            float mk = sm[ln][k];
            float hk = sh[ln][k];
            gir[i] += mk * wi.x; giz[i] += mk * wi.y; gin[i] += mk * wi.z;
            ghr[i] += hk * wh.x; ghz[i] += hk * wh.y; ghn[i] += hk * wh.z;
        }
    }

#pragma unroll
    for (int i = 0; i < 4; i++) {
        int ln = ng + 4 * i;
        float r  = sigm(gir[i] + ghr[i]);
        float z  = sigm(giz[i] + ghz[i]);
        float nn = tanhf(gin[i] + r * ghn[i]);
        float hv = (1.f - z) * nn + z * sh[ln][f];
        g_h[(nb + ln) * D + f] = hv;
        g_h_h[(nb + ln) * D + f] = __float2half(hv);
    }
}

// ---------------- set2set + head ----------------

__global__ void k_s2s_init(const float* __restrict__ lbih,
                           const float* __restrict__ lbhh) {
    int t = threadIdx.x;
    if (t < D) {
        float gi = lbih[t]         + lbhh[t];
        float gg = lbih[2 * D + t] + lbhh[2 * D + t];
        float go = lbih[3 * D + t] + lbhh[3 * D + t];
        float cl = sigm(gi) * tanhf(gg);
        g_q[t] = sigm(go) * tanhf(cl);
    }
    if (t < BG) { g_emax[t] = -3.4e38f; g_asum[t] = 0.f; }
    for (int i = t; i < BG * D; i += blockDim.x) g_rpool[i] = 0.f;
}

__global__ void k_dot(const int* __restrict__ batch) {
    int lane = threadIdx.x & 31;
    int warp = threadIdx.x >> 5;
    int n = blockIdx.x * 8 + warp;
    if (n >= N_NODES) return;
    float v = g_h[n * D + lane] * g_q[lane] + g_h[n * D + 32 + lane] * g_q[32 + lane];
#pragma unroll
    for (int o = 16; o > 0; o >>= 1) v += __shfl_down_sync(0xFFFFFFFFu, v, o);
    if (lane == 0) {
        g_e[n] = v;
        atomicMaxF(&g_emax[batch[n]], v);
    }
}

__global__ void k_exp(const int* __restrict__ batch) {
    int n = blockIdx.x * blockDim.x + threadIdx.x;
    if (n >= N_NODES) return;
    int g = batch[n];
    float a = expf(g_e[n] - g_emax[g]);
    g_a[n] = a;
    atomicAdd(&g_asum[g], a);
}

__global__ void k_pool(const int* __restrict__ batch) {
    int idx = blockIdx.x * blockDim.x + threadIdx.x;
    if (idx >= N_NODES * D) return;
    int n = idx >> 6, f = idx & 63;
    int g = batch[n];
    float w = g_a[n] / g_asum[g];
    atomicAdd(&g_rpool[g * D + f], w * g_h[idx]);
}

__global__ void k_out(const float* __restrict__ Wout,
                      const float* __restrict__ bout,
                      float* __restrict__ out) {
    int t = threadIdx.x;
    if (t >= BG * 2) return;
    int b = t >> 1, c = t & 1;
    float acc = bout[c];
#pragma unroll 8
    for (int j = 0; j < D; j++) {
        acc += g_q[j] * Wout[j * 2 + c];
        acc += g_rpool[b * D + j] * Wout[(D + j) * 2 + c];
    }
    out[b * 2 + c] = acc;
}

// ---------------- launch ----------------

extern "C" void kernel_launch(void* const* d_in, const int* in_sizes, int n_in,
                              void* d_out, int out_size) {
    const float* x      = (const float*)d_in[0];
    const float* ea     = (const float*)d_in[1];
    const int*   ei     = (const int*)d_in[2];
    const int*   batch  = (const int*)d_in[3];
    const float* W0     = (const float*)d_in[4];
    const float* b0     = (const float*)d_in[5];
    const float* We1    = (const float*)d_in[6];
    const float* be1    = (const float*)d_in[7];
    const float* We2    = (const float*)d_in[8];
    const float* be2    = (const float*)d_in[9];
    const float* root   = (const float*)d_in[10];
    const float* conv_b = (const float*)d_in[11];
    const float* Wih    = (const float*)d_in[12];
    const float* Whh    = (const float*)d_in[13];
    const float* bih    = (const float*)d_in[14];
    const float* bhh    = (const float*)d_in[15];
    const float* lbih   = (const float*)d_in[18];
    const float* lbhh   = (const float*)d_in[19];
    const float* Wout   = (const float*)d_in[20];
    const float* bout   = (const float*)d_in[21];
    float* out = (float*)d_out;
    (void)in_sizes; (void)n_in; (void)out_size;

    // launch order: index 3 (ncu capture slot) = first k_msg_fused
    k_node_init<<<(N_NODES * D) / 256, 256>>>(x, W0, b0);           // 0
    k_edge_init<<<(N_EDGES * D) / 256, 256>>>(ea, We1, be1, ei);    // 1
    k_prep_bt<<<(NCHUNK * 4096) / 256, 256>>>(We2, be2);            // 2
    k_msg_fused<<<N_EDGES / 64, 128>>>(ei);                         // 3  <- profiled
    k_prep_gru<<<(D * D * 4) / 256, 256>>>(Wih, Whh);               // 4
    k_node_update<<<N_NODES / 16, 256>>>(root, conv_b, bih, bhh);   // 5

    for (int it = 1; it < 6; it++) {
        k_msg_fused<<<N_EDGES / 64, 128>>>(ei);
        k_node_update<<<N_NODES / 16, 256>>>(root, conv_b, bih, bhh);
    }

    k_s2s_init<<<1, 256>>>(lbih, lbhh);
    k_dot<<<N_NODES / 8, 256>>>(batch);
    k_exp<<<(N_NODES + 255) / 256, 256>>>(batch);
    k_pool<<<(N_NODES * D) / 256, 256>>>(batch);
    k_out<<<1, 64>>>(Wout, bout, out);
}

// round 10
// speedup vs baseline: 1.3647x; 1.3647x over previous
#include <cuda_runtime.h>
#include <cuda_fp16.h>
#include <math.h>
#include <stdint.h>

#define N_NODES 4096
#define N_EDGES 16384
#define D       64
#define BG      16
#define SLOPE   0.01f

#define TW      4160            // T row width: 4096 (k*64+f) + 64 bias cols
#define TWPAD   4352            // padded to 17*256 for GEMM tiling

// ---------------- device scratch ----------------
__device__ __half g_T[(size_t)N_NODES * TW];     // 34 MB per-node transformed table
__device__ __half g_We2RT[TWPAD * D];            // [c][d] reshaped We2 (+bias cols)
__device__ __half g_he_h[N_EDGES * D];
__device__ __half g_h_h[N_NODES * D];            // fp16 mirror of h
__device__ float g_h[N_NODES * D];
__device__ float g_agg[N_NODES * D];
__device__ float g_deg[N_NODES];
__device__ float g_Wi4[D * D * 4];
__device__ float g_Wh4[D * D * 4];
__device__ float g_q[D];
__device__ float g_e[N_NODES];
__device__ float g_a[N_NODES];
__device__ float g_emax[BG];
__device__ float g_asum[BG];
__device__ float g_rpool[BG * D];

__device__ __forceinline__ float lrelu(float x) { return x >= 0.f ? x : SLOPE * x; }
__device__ __forceinline__ float sigm(float x)  { return 1.f / (1.f + expf(-x)); }

__device__ __forceinline__ void atomicMaxF(float* addr, float v) {
    int* ai = (int*)addr;
    int old = *ai;
    while (__int_as_float(old) < v) {
        int assumed = old;
        old = atomicCAS(ai, assumed, __float_as_int(v));
        if (old == assumed) break;
    }
}

__device__ __forceinline__ void mma16816(float c[4],
                                         uint32_t a0, uint32_t a1, uint32_t a2, uint32_t a3,
                                         uint32_t b0, uint32_t b1) {
    asm volatile(
        "mma.sync.aligned.m16n8k16.row.col.f32.f16.f16.f32 "
        "{%0,%1,%2,%3}, {%4,%5,%6,%7}, {%8,%9}, {%0,%1,%2,%3};"
        : "+f"(c[0]), "+f"(c[1]), "+f"(c[2]), "+f"(c[3])
        : "r"(a0), "r"(a1), "r"(a2), "r"(a3), "r"(b0), "r"(b1));
}

__device__ __forceinline__ void ldsm_x4(uint32_t& r0, uint32_t& r1,
                                        uint32_t& r2, uint32_t& r3,
                                        const void* smem_ptr) {
    uint32_t addr;
    asm("{ .reg .u64 t; cvta.to.shared.u64 t, %1; cvt.u32.u64 %0, t; }"
        : "=r"(addr) : "l"(smem_ptr));
    asm volatile("ldmatrix.sync.aligned.m8n8.x4.shared.b16 {%0,%1,%2,%3}, [%4];"
                 : "=r"(r0), "=r"(r1), "=r"(r2), "=r"(r3) : "r"(addr));
}

// ---------------- prep kernels ----------------

// h0 = lrelu(x @ W0 + b0); also zero agg + deg
__global__ void k_node_init(const float* __restrict__ x,
                            const float* __restrict__ W0,
                            const float* __restrict__ b0) {
    int idx = blockIdx.x * blockDim.x + threadIdx.x;
    if (idx >= N_NODES * D) return;
    int n = idx >> 6, f = idx & 63;
    float acc = b0[f];
    acc += x[n * 3 + 0] * W0[0 * D + f];
    acc += x[n * 3 + 1] * W0[1 * D + f];
    acc += x[n * 3 + 2] * W0[2 * D + f];
    float v = lrelu(acc);
    g_h[idx] = v;
    g_h_h[idx] = __float2half(v);
    g_agg[idx] = 0.f;
    if (f == 0) g_deg[n] = 0.f;
}

__global__ void k_edge_init(const float* __restrict__ ea,
                            const float* __restrict__ We1,
                            const float* __restrict__ be1,
                            const int* __restrict__ ei) {
    int idx = blockIdx.x * blockDim.x + threadIdx.x;
    if (idx >= N_EDGES * D) return;
    int e = idx >> 6, f = idx & 63;
    float acc = be1[f];
    acc += ea[e * 4 + 0] * We1[0 * D + f];
    acc += ea[e * 4 + 1] * We1[1 * D + f];
    acc += ea[e * 4 + 2] * We1[2 * D + f];
    acc += ea[e * 4 + 3] * We1[3 * D + f];
    g_he_h[idx] = __float2half(lrelu(acc));
    if (f == 0) {
        int dst = ei[N_EDGES + e];
        atomicAdd(&g_deg[dst], 1.f);
    }
}

// We2RT[c][d]: c = k*64+f -> We2[k][d*64+f]; c in [4096,4160): be2[d*64+(c-4096)]; pad 0.
__global__ void k_prep_we2rt(const float* __restrict__ We2,
                             const float* __restrict__ be2) {
    int idx = blockIdx.x * blockDim.x + threadIdx.x;
    if (idx >= TWPAD * D) return;
    int d = idx & 63, c = idx >> 6;
    float v = 0.f;
    if (c < 4096) {
        int k = c >> 6, f = c & 63;
        v = We2[k * 4096 + d * 64 + f];
    } else if (c < TW) {
        int f = c - 4096;
        v = be2[d * 64 + f];
    }
    g_We2RT[c * D + d] = __float2half(v);
}

__global__ void k_prep_gru(const float* __restrict__ Wih,
                           const float* __restrict__ Whh) {
    int idx = blockIdx.x * blockDim.x + threadIdx.x;
    if (idx >= D * D * 4) return;
    int gg = idx & 3, f = (idx >> 2) & 63, k = idx >> 8;
    float vi = 0.f, vh = 0.f;
    if (gg < 3) {
        vi = Wih[(gg * 64 + f) * 64 + k];
        vh = Whh[(gg * 64 + f) * 64 + k];
    }
    g_Wi4[idx] = vi;
    g_Wh4[idx] = vh;
}

// ---------------- per-iteration T GEMM (tensor cores, staged coalesced epilogue) ----------------
// T[n][c] = sum_d h[n,d] * We2RT[c][d], fp16 out.
// Block: 128 nodes x 256 cols; dynamic smem: sBT 256x72, sA 64x72, sStage 64x264.
__global__ void __launch_bounds__(512, 2) k_t_gemm() {
    extern __shared__ __half smem[];
    __half* sBT = smem;                 // [256][72]
    __half* sA  = smem + 256 * 72;      // [64][72]
    __half* sSt = smem + 320 * 72;      // [64][264]
    int nbase = blockIdx.x * 256;
    int mbase0 = blockIdx.y * 128;
    int tid = threadIdx.x;

#pragma unroll
    for (int i = 0; i < 4; i++) {
        int u = tid + i * 512;
        int row = u >> 3, ch = u & 7;
        *(uint4*)&sBT[row * 72 + ch * 8] = *(const uint4*)&g_We2RT[(nbase + row) * D + ch * 8];
    }

    int warp = tid >> 5, lane = tid & 31;
    int wm = warp & 3, wn = warp >> 2;
    int g = lane >> 2, tig = lane & 3;
    int a_row = (lane & 7) + ((lane & 8) ? 8 : 0);
    int a_col8 = (lane & 16) ? 8 : 0;
    int b_row = (lane & 7) + ((lane & 16) ? 8 : 0);
    int b_col8 = (lane & 8) ? 8 : 0;

#pragma unroll
    for (int ms = 0; ms < 2; ms++) {
        int mbase = mbase0 + ms * 64;
        __syncthreads();   // protect sA/sStage reuse (and first-time sBT visibility)
        {
            int row = tid >> 3, ch = tid & 7;
            *(uint4*)&sA[row * 72 + ch * 8] = *(const uint4*)&g_h_h[(mbase + row) * D + ch * 8];
        }
        __syncthreads();

        float c[8][4];
#pragma unroll
        for (int j = 0; j < 8; j++) { c[j][0] = c[j][1] = c[j][2] = c[j][3] = 0.f; }

#pragma unroll
        for (int s = 0; s < 4; s++) {
            int k0 = s * 16;
            uint32_t a0, a1, a2, a3;
            ldsm_x4(a0, a1, a2, a3, &sA[(wm * 16 + a_row) * 72 + k0 + a_col8]);
#pragma unroll
            for (int jp = 0; jp < 4; jp++) {
                uint32_t b0, b1, b2, b3;
                ldsm_x4(b0, b1, b2, b3,
                        &sBT[(wn * 64 + jp * 16 + b_row) * 72 + k0 + b_col8]);
                mma16816(c[2 * jp],     a0, a1, a2, a3, b0, b1);
                mma16816(c[2 * jp + 1], a0, a1, a2, a3, b2, b3);
            }
        }

        // stage fragments into smem (conflict-free: bank = 4g + tig + const)
#pragma unroll
        for (int j = 0; j < 8; j++) {
            int col = wn * 64 + j * 8 + 2 * tig;
            int r0 = wm * 16 + g;
            *(__half2*)&sSt[r0 * 264 + col] = __floats2half2_rn(c[j][0], c[j][1]);
            *(__half2*)&sSt[(r0 + 8) * 264 + col] = __floats2half2_rn(c[j][2], c[j][3]);
        }
        __syncthreads();

        // coalesced copy-out: full 128B gmem rows
#pragma unroll
        for (int i = 0; i < 4; i++) {
            int u = tid + i * 512;
            int row = u >> 5, seg = u & 31;
            int col = nbase + seg * 8;
            if (col < TW)
                *(uint4*)&g_T[(size_t)(mbase + row) * TW + col] =
                    *(uint4*)&sSt[row * 264 + seg * 8];
        }
    }
}

// ---------------- loop kernels ----------------

// msg[e,f] = sum_k he[e,k] * T[src, k*64+f] + T[src, 4096+f]; scatter to agg.
// 16 edges/block (256 thr): 2 edges/warp, 16 lanes/edge, 4 cols/lane (LDG.64).
__global__ void k_msg(const int* __restrict__ ei) {
    int tid = threadIdx.x;
    int warp = tid >> 5, lane = tid & 31;
    int half = lane >> 4, sl = lane & 15;
    int le = warp * 2 + half;
    int e = blockIdx.x * 16 + le;
    __shared__ float sx[16][D];
#pragma unroll
    for (int i = 0; i < 4; i++) {
        int idx = tid + i * 256;
        int l2 = idx >> 6, k = idx & 63;
        sx[l2][k] = __half2float(g_he_h[(blockIdx.x * 16 + l2) * D + k]);
    }
    __syncthreads();

    int src = ei[e];
    int dst = ei[N_EDGES + e];
    const __half* __restrict__ T = g_T + (size_t)src * TW;

    float a0, a1, a2, a3;
    {
        uint2 b = *(const uint2*)&T[4096 + 4 * sl];
        float2 b01 = __half22float2(*(__half2*)&b.x);
        float2 b23 = __half22float2(*(__half2*)&b.y);
        a0 = b01.x; a1 = b01.y; a2 = b23.x; a3 = b23.y;
    }
#pragma unroll 8
    for (int k = 0; k < D; k++) {
        uint2 w = *(const uint2*)&T[k * 64 + 4 * sl];
        float2 w01 = __half22float2(*(__half2*)&w.x);
        float2 w23 = __half22float2(*(__half2*)&w.y);
        float hv = sx[le][k];
        a0 = fmaf(hv, w01.x, a0);
        a1 = fmaf(hv, w01.y, a1);
        a2 = fmaf(hv, w23.x, a2);
        a3 = fmaf(hv, w23.y, a3);
    }
    float* agg = &g_agg[dst * D + 4 * sl];
    atomicAdd(agg + 0, a0);
    atomicAdd(agg + 1, a1);
    atomicAdd(agg + 2, a2);
    atomicAdd(agg + 3, a3);
}

// node update: m = lrelu(agg/deg + h@root + conv_b); GRU; h <- new; agg <- 0
__global__ void k_node_update(const float* __restrict__ root,
                              const float* __restrict__ conv_b,
                              const float* __restrict__ bih,
                              const float* __restrict__ bhh) {
    __shared__ float sh[16][D];
    __shared__ float sm[16][D];
    __shared__ float sroot[D][D];
    int nb = blockIdx.x * 16;
    int tid = threadIdx.x;
    int f = tid & 63, ng = tid >> 6;

#pragma unroll
    for (int i = 0; i < 4; i++) {
        int ln = ng + 4 * i;
        sh[ln][f] = g_h[(nb + ln) * D + f];
    }
#pragma unroll
    for (int i = 0; i < 16; i++) {
        int idx = tid + i * 256;
        sroot[idx >> 6][idx & 63] = root[idx];
    }
    __syncthreads();

    float cb = conv_b[f];
#pragma unroll
    for (int i = 0; i < 4; i++) {
        int ln = ng + 4 * i;
        int n = nb + ln;
        float invd = 1.f / fmaxf(g_deg[n], 1.f);
        float acc = g_agg[n * D + f] * invd + cb;
        g_agg[n * D + f] = 0.f;
#pragma unroll 8
        for (int d = 0; d < D; d++) acc += sh[ln][d] * sroot[d][f];
        sm[ln][f] = lrelu(acc);
    }
    __syncthreads();

    float gir[4], giz[4], gin[4], ghr[4], ghz[4], ghn[4];
    float bir = bih[f], biz = bih[D + f], bin = bih[2 * D + f];
    float bhr = bhh[f], bhz = bhh[D + f], bhn = bhh[2 * D + f];
#pragma unroll
    for (int i = 0; i < 4; i++) {
        gir[i] = bir; giz[i] = biz; gin[i] = bin;
        ghr[i] = bhr; ghz[i] = bhz; ghn[i] = bhn;
    }

#pragma unroll 4
    for (int k = 0; k < D; k++) {
        float4 wi = *(const float4*)&g_Wi4[(k * D + f) * 4];
        float4 wh = *(const float4*)&g_Wh4[(k * D + f) * 4];
#pragma unroll
        for (int i = 0; i < 4; i++) {
            int ln = ng + 4 * i;
            float mk = sm[ln][k];
            float hk = sh[ln][k];
            gir[i] += mk * wi.x; giz[i] += mk * wi.y; gin[i] += mk * wi.z;
            ghr[i] += hk * wh.x; ghz[i] += hk * wh.y; ghn[i] += hk * wh.z;
        }
    }

#pragma unroll
    for (int i = 0; i < 4; i++) {
        int ln = ng + 4 * i;
        float r  = sigm(gir[i] + ghr[i]);
        float z  = sigm(giz[i] + ghz[i]);
        float nn = tanhf(gin[i] + r * ghn[i]);
        float hv = (1.f - z) * nn + z * sh[ln][f];
        g_h[(nb + ln) * D + f] = hv;
        g_h_h[(nb + ln) * D + f] = __float2half(hv);
    }
}

// ---------------- set2set + head ----------------

__global__ void k_s2s_init(const float* __restrict__ lbih,
                           const float* __restrict__ lbhh) {
    int t = threadIdx.x;
    if (t < D) {
        float gi = lbih[t]         + lbhh[t];
        float gg = lbih[2 * D + t] + lbhh[2 * D + t];
        float go = lbih[3 * D + t] + lbhh[3 * D + t];
        float cl = sigm(gi) * tanhf(gg);
        g_q[t] = sigm(go) * tanhf(cl);
    }
    if (t < BG) { g_emax[t] = -3.4e38f; g_asum[t] = 0.f; }
    for (int i = t; i < BG * D; i += blockDim.x) g_rpool[i] = 0.f;
}

__global__ void k_dot(const int* __restrict__ batch) {
    int lane = threadIdx.x & 31;
    int warp = threadIdx.x >> 5;
    int n = blockIdx.x * 8 + warp;
    if (n >= N_NODES) return;
    float v = g_h[n * D + lane] * g_q[lane] + g_h[n * D + 32 + lane] * g_q[32 + lane];
#pragma unroll
    for (int o = 16; o > 0; o >>= 1) v += __shfl_down_sync(0xFFFFFFFFu, v, o);
    if (lane == 0) {
        g_e[n] = v;
        atomicMaxF(&g_emax[batch[n]], v);
    }
}

__global__ void k_exp(const int* __restrict__ batch) {
    int n = blockIdx.x * blockDim.x + threadIdx.x;
    if (n >= N_NODES) return;
    int g = batch[n];
    float a = expf(g_e[n] - g_emax[g]);
    g_a[n] = a;
    atomicAdd(&g_asum[g], a);
}

__global__ void k_pool(const int* __restrict__ batch) {
    int idx = blockIdx.x * blockDim.x + threadIdx.x;
    if (idx >= N_NODES * D) return;
    int n = idx >> 6, f = idx & 63;
    int g = batch[n];
    float w = g_a[n] / g_asum[g];
    atomicAdd(&g_rpool[g * D + f], w * g_h[idx]);
}

__global__ void k_out(const float* __restrict__ Wout,
                      const float* __restrict__ bout,
                      float* __restrict__ out) {
    int t = threadIdx.x;
    if (t >= BG * 2) return;
    int b = t >> 1, c = t & 1;
    float acc = bout[c];
#pragma unroll 8
    for (int j = 0; j < D; j++) {
        acc += g_q[j] * Wout[j * 2 + c];
        acc += g_rpool[b * D + j] * Wout[(D + j) * 2 + c];
    }
    out[b * 2 + c] = acc;
}

// ---------------- launch ----------------

extern "C" void kernel_launch(void* const* d_in, const int* in_sizes, int n_in,
                              void* d_out, int out_size) {
    const float* x      = (const float*)d_in[0];
    const float* ea     = (const float*)d_in[1];
    const int*   ei     = (const int*)d_in[2];
    const int*   batch  = (const int*)d_in[3];
    const float* W0     = (const float*)d_in[4];
    const float* b0     = (const float*)d_in[5];
    const float* We1    = (const float*)d_in[6];
    const float* be1    = (const float*)d_in[7];
    const float* We2    = (const float*)d_in[8];
    const float* be2    = (const float*)d_in[9];
    const float* root   = (const float*)d_in[10];
    const float* conv_b = (const float*)d_in[11];
    const float* Wih    = (const float*)d_in[12];
    const float* Whh    = (const float*)d_in[13];
    const float* bih    = (const float*)d_in[14];
    const float* bhh    = (const float*)d_in[15];
    const float* lbih   = (const float*)d_in[18];
    const float* lbhh   = (const float*)d_in[19];
    const float* Wout   = (const float*)d_in[20];
    const float* bout   = (const float*)d_in[21];
    float* out = (float*)d_out;
    (void)in_sizes; (void)n_in; (void)out_size;

    const int TGEMM_SMEM = (256 * 72 + 64 * 72 + 64 * 264) * (int)sizeof(__half); // 79872
    cudaFuncSetAttribute(k_t_gemm, cudaFuncAttributeMaxDynamicSharedMemorySize, TGEMM_SMEM);

    dim3 tgrid(17, N_NODES / 128);

    // launch order: index 3 (ncu capture slot) = first k_t_gemm
    k_node_init<<<(N_NODES * D) / 256, 256>>>(x, W0, b0);           // 0
    k_edge_init<<<(N_EDGES * D) / 256, 256>>>(ea, We1, be1, ei);    // 1
    k_prep_we2rt<<<(TWPAD * D) / 256, 256>>>(We2, be2);             // 2
    k_t_gemm<<<tgrid, 512, TGEMM_SMEM>>>();                         // 3  <- profiled
    k_prep_gru<<<(D * D * 4) / 256, 256>>>(Wih, Whh);               // 4
    k_msg<<<N_EDGES / 16, 256>>>(ei);                               // 5
    k_node_update<<<N_NODES / 16, 256>>>(root, conv_b, bih, bhh);   // 6

    for (int it = 1; it < 6; it++) {
        k_t_gemm<<<tgrid, 512, TGEMM_SMEM>>>();
        k_msg<<<N_EDGES / 16, 256>>>(ei);
        k_node_update<<<N_NODES / 16, 256>>>(root, conv_b, bih, bhh);
    }

    k_s2s_init<<<1, 256>>>(lbih, lbhh);
    k_dot<<<N_NODES / 8, 256>>>(batch);
    k_exp<<<(N_NODES + 255) / 256, 256>>>(batch);
    k_pool<<<(N_NODES * D) / 256, 256>>>(batch);
    k_out<<<1, 64>>>(Wout, bout, out);
}

// round 11
// speedup vs baseline: 1.3856x; 1.0153x over previous
#include <cuda_runtime.h>
#include <cuda_fp16.h>
#include <math.h>
#include <stdint.h>

#define N_NODES 4096
#define N_EDGES 16384
#define D       64
#define BG      16
#define SLOPE   0.01f

#define TW      4160            // T row width: 4096 (k*64+f) + 64 bias cols
#define TWPAD   4352            // padded to 17*256 for GEMM tiling

// ---------------- device scratch ----------------
__device__ __half g_T[(size_t)N_NODES * TW];     // 34 MB per-node transformed table
__device__ __half g_We2RT[TWPAD * D];            // [c][d] reshaped We2 (+bias cols)
__device__ __half g_he_h[N_EDGES * D];
__device__ __half g_h_h[N_NODES * D];            // fp16 mirror of h
__device__ float g_h[N_NODES * D];
__device__ float g_agg[N_NODES * D];
__device__ float g_deg[N_NODES];
__device__ float g_Wi4[D * D * 4];
__device__ float g_Wh4[D * D * 4];
__device__ float g_q[D];
__device__ float g_e[N_NODES];
__device__ float g_a[N_NODES];
__device__ float g_emax[BG];
__device__ float g_asum[BG];
__device__ float g_rpool[BG * D];

__device__ __forceinline__ float lrelu(float x) { return x >= 0.f ? x : SLOPE * x; }
__device__ __forceinline__ float sigm(float x)  { return 1.f / (1.f + expf(-x)); }

__device__ __forceinline__ void atomicMaxF(float* addr, float v) {
    int* ai = (int*)addr;
    int old = *ai;
    while (__int_as_float(old) < v) {
        int assumed = old;
        old = atomicCAS(ai, assumed, __float_as_int(v));
        if (old == assumed) break;
    }
}

__device__ __forceinline__ void mma16816(float c[4],
                                         uint32_t a0, uint32_t a1, uint32_t a2, uint32_t a3,
                                         uint32_t b0, uint32_t b1) {
    asm volatile(
        "mma.sync.aligned.m16n8k16.row.col.f32.f16.f16.f32 "
        "{%0,%1,%2,%3}, {%4,%5,%6,%7}, {%8,%9}, {%0,%1,%2,%3};"
        : "+f"(c[0]), "+f"(c[1]), "+f"(c[2]), "+f"(c[3])
        : "r"(a0), "r"(a1), "r"(a2), "r"(a3), "r"(b0), "r"(b1));
}

__device__ __forceinline__ void ldsm_x4(uint32_t& r0, uint32_t& r1,
                                        uint32_t& r2, uint32_t& r3,
                                        const void* smem_ptr) {
    uint32_t addr;
    asm("{ .reg .u64 t; cvta.to.shared.u64 t, %1; cvt.u32.u64 %0, t; }"
        : "=r"(addr) : "l"(smem_ptr));
    asm volatile("ldmatrix.sync.aligned.m8n8.x4.shared.b16 {%0,%1,%2,%3}, [%4];"
                 : "=r"(r0), "=r"(r1), "=r"(r2), "=r"(r3) : "r"(addr));
}

// ---------------- prep kernels ----------------

// h0 = lrelu(x @ W0 + b0); also zero agg + deg
__global__ void k_node_init(const float* __restrict__ x,
                            const float* __restrict__ W0,
                            const float* __restrict__ b0) {
    int idx = blockIdx.x * blockDim.x + threadIdx.x;
    if (idx >= N_NODES * D) return;
    int n = idx >> 6, f = idx & 63;
    float acc = b0[f];
    acc += x[n * 3 + 0] * W0[0 * D + f];
    acc += x[n * 3 + 1] * W0[1 * D + f];
    acc += x[n * 3 + 2] * W0[2 * D + f];
    float v = lrelu(acc);
    g_h[idx] = v;
    g_h_h[idx] = __float2half(v);
    g_agg[idx] = 0.f;
    if (f == 0) g_deg[n] = 0.f;
}

__global__ void k_edge_init(const float* __restrict__ ea,
                            const float* __restrict__ We1,
                            const float* __restrict__ be1,
                            const int* __restrict__ ei) {
    int idx = blockIdx.x * blockDim.x + threadIdx.x;
    if (idx >= N_EDGES * D) return;
    int e = idx >> 6, f = idx & 63;
    float acc = be1[f];
    acc += ea[e * 4 + 0] * We1[0 * D + f];
    acc += ea[e * 4 + 1] * We1[1 * D + f];
    acc += ea[e * 4 + 2] * We1[2 * D + f];
    acc += ea[e * 4 + 3] * We1[3 * D + f];
    g_he_h[idx] = __float2half(lrelu(acc));
    if (f == 0) {
        int dst = ei[N_EDGES + e];
        atomicAdd(&g_deg[dst], 1.f);
    }
}

// We2RT[c][d]: c = k*64+f -> We2[k][d*64+f]; c in [4096,4160): be2[d*64+(c-4096)]; pad 0.
__global__ void k_prep_we2rt(const float* __restrict__ We2,
                             const float* __restrict__ be2) {
    int idx = blockIdx.x * blockDim.x + threadIdx.x;
    if (idx >= TWPAD * D) return;
    int d = idx & 63, c = idx >> 6;
    float v = 0.f;
    if (c < 4096) {
        int k = c >> 6, f = c & 63;
        v = We2[k * 4096 + d * 64 + f];
    } else if (c < TW) {
        int f = c - 4096;
        v = be2[d * 64 + f];
    }
    g_We2RT[c * D + d] = __float2half(v);
}

__global__ void k_prep_gru(const float* __restrict__ Wih,
                           const float* __restrict__ Whh) {
    int idx = blockIdx.x * blockDim.x + threadIdx.x;
    if (idx >= D * D * 4) return;
    int gg = idx & 3, f = (idx >> 2) & 63, k = idx >> 8;
    float vi = 0.f, vh = 0.f;
    if (gg < 3) {
        vi = Wih[(gg * 64 + f) * 64 + k];
        vh = Whh[(gg * 64 + f) * 64 + k];
    }
    g_Wi4[idx] = vi;
    g_Wh4[idx] = vh;
}

// ---------------- per-iteration T GEMM ----------------
// T[n][c] = sum_d h[n,d] * We2RT[c][d], fp16 out.
// Block: 256 nodes x 256 cols (4 x 64-row phases); 512 thr; warps 2wm x 8wn, m32 x n32.
// grid = 17 x 16 = 272 blocks -> single wave at 2 blocks/SM.
__global__ void __launch_bounds__(512, 2) k_t_gemm() {
    extern __shared__ __half smem[];
    __half* sBT = smem;                 // [256][72]
    __half* sA  = smem + 256 * 72;      // [64][72]
    __half* sSt = smem + 320 * 72;      // [64][264]
    int nbase = blockIdx.x * 256;
    int mbase0 = blockIdx.y * 256;
    int tid = threadIdx.x;

#pragma unroll
    for (int i = 0; i < 4; i++) {
        int u = tid + i * 512;
        int row = u >> 3, ch = u & 7;
        *(uint4*)&sBT[row * 72 + ch * 8] = *(const uint4*)&g_We2RT[(nbase + row) * D + ch * 8];
    }

    int warp = tid >> 5, lane = tid & 31;
    int wm = warp & 1, wn = warp >> 1;        // 2 x 8 warp grid
    int g = lane >> 2, tig = lane & 3;
    int a_row = (lane & 7) + ((lane & 8) ? 8 : 0);
    int a_col8 = (lane & 16) ? 8 : 0;
    int b_row = (lane & 7) + ((lane & 16) ? 8 : 0);
    int b_col8 = (lane & 8) ? 8 : 0;

#pragma unroll
    for (int ms = 0; ms < 4; ms++) {
        int mbase = mbase0 + ms * 64;
        __syncthreads();   // protect sA/sStage reuse (and first-time sBT visibility)
        {
            int row = tid >> 3, ch = tid & 7;
            *(uint4*)&sA[row * 72 + ch * 8] = *(const uint4*)&g_h_h[(mbase + row) * D + ch * 8];
        }
        __syncthreads();

        float c[2][4][4];
#pragma unroll
        for (int t = 0; t < 2; t++)
#pragma unroll
            for (int j = 0; j < 4; j++)
                c[t][j][0] = c[t][j][1] = c[t][j][2] = c[t][j][3] = 0.f;

#pragma unroll
        for (int s = 0; s < 4; s++) {
            int k0 = s * 16;
            uint32_t a[2][4], b[2][4];
#pragma unroll
            for (int t = 0; t < 2; t++)
                ldsm_x4(a[t][0], a[t][1], a[t][2], a[t][3],
                        &sA[(wm * 32 + t * 16 + a_row) * 72 + k0 + a_col8]);
#pragma unroll
            for (int jp = 0; jp < 2; jp++)
                ldsm_x4(b[jp][0], b[jp][1], b[jp][2], b[jp][3],
                        &sBT[(wn * 32 + jp * 16 + b_row) * 72 + k0 + b_col8]);
#pragma unroll
            for (int t = 0; t < 2; t++)
#pragma unroll
                for (int jp = 0; jp < 2; jp++) {
                    mma16816(c[t][2 * jp],     a[t][0], a[t][1], a[t][2], a[t][3],
                             b[jp][0], b[jp][1]);
                    mma16816(c[t][2 * jp + 1], a[t][0], a[t][1], a[t][2], a[t][3],
                             b[jp][2], b[jp][3]);
                }
        }

        // stage fragments into smem (conflict-free: bank = 4g + tig + const)
#pragma unroll
        for (int t = 0; t < 2; t++)
#pragma unroll
            for (int j = 0; j < 4; j++) {
                int col = wn * 32 + j * 8 + 2 * tig;
                int r0 = wm * 32 + t * 16 + g;
                *(__half2*)&sSt[r0 * 264 + col] = __floats2half2_rn(c[t][j][0], c[t][j][1]);
                *(__half2*)&sSt[(r0 + 8) * 264 + col] = __floats2half2_rn(c[t][j][2], c[t][j][3]);
            }
        __syncthreads();

        // coalesced copy-out: full 128B gmem rows
#pragma unroll
        for (int i = 0; i < 4; i++) {
            int u = tid + i * 512;
            int row = u >> 5, seg = u & 31;
            int col = nbase + seg * 8;
            if (col < TW)
                *(uint4*)&g_T[(size_t)(mbase + row) * TW + col] =
                    *(uint4*)&sSt[row * 264 + seg * 8];
        }
    }
}

// ---------------- loop kernels ----------------

// msg[e,f] = sum_k he[e,k] * T[src, k*64+f] + T[src, 4096+f]; scatter to agg.
// 16 edges/block (256 thr): 2 edges/warp, 16 lanes/edge, 4 cols/lane (LDG.64).
__global__ void k_msg(const int* __restrict__ ei) {
    int tid = threadIdx.x;
    int warp = tid >> 5, lane = tid & 31;
    int half = lane >> 4, sl = lane & 15;
    int le = warp * 2 + half;
    int e = blockIdx.x * 16 + le;
    __shared__ float sx[16][D];
#pragma unroll
    for (int i = 0; i < 4; i++) {
        int idx = tid + i * 256;
        int l2 = idx >> 6, k = idx & 63;
        sx[l2][k] = __half2float(g_he_h[(blockIdx.x * 16 + l2) * D + k]);
    }
    __syncthreads();

    int src = ei[e];
    int dst = ei[N_EDGES + e];
    const __half* __restrict__ T = g_T + (size_t)src * TW;

    float a0, a1, a2, a3;
    {
        uint2 b = *(const uint2*)&T[4096 + 4 * sl];
        float2 b01 = __half22float2(*(__half2*)&b.x);
        float2 b23 = __half22float2(*(__half2*)&b.y);
        a0 = b01.x; a1 = b01.y; a2 = b23.x; a3 = b23.y;
    }
#pragma unroll 8
    for (int k = 0; k < D; k++) {
        uint2 w = *(const uint2*)&T[k * 64 + 4 * sl];
        float2 w01 = __half22float2(*(__half2*)&w.x);
        float2 w23 = __half22float2(*(__half2*)&w.y);
        float hv = sx[le][k];
        a0 = fmaf(hv, w01.x, a0);
        a1 = fmaf(hv, w01.y, a1);
        a2 = fmaf(hv, w23.x, a2);
        a3 = fmaf(hv, w23.y, a3);
    }
    float* agg = &g_agg[dst * D + 4 * sl];
    atomicAdd(agg + 0, a0);
    atomicAdd(agg + 1, a1);
    atomicAdd(agg + 2, a2);
    atomicAdd(agg + 3, a3);
}

// node update: m = lrelu(agg/deg + h@root + conv_b); GRU; h <- new; agg <- 0
__global__ void k_node_update(const float* __restrict__ root,
                              const float* __restrict__ conv_b,
                              const float* __restrict__ bih,
                              const float* __restrict__ bhh) {
    __shared__ float sh[16][D];
    __shared__ float sm[16][D];
    __shared__ float sroot[D][D];
    int nb = blockIdx.x * 16;
    int tid = threadIdx.x;
    int f = tid & 63, ng = tid >> 6;

#pragma unroll
    for (int i = 0; i < 4; i++) {
        int ln = ng + 4 * i;
        sh[ln][f] = g_h[(nb + ln) * D + f];
    }
#pragma unroll
    for (int i = 0; i < 16; i++) {
        int idx = tid + i * 256;
        sroot[idx >> 6][idx & 63] = root[idx];
    }
    __syncthreads();

    float cb = conv_b[f];
#pragma unroll
    for (int i = 0; i < 4; i++) {
        int ln = ng + 4 * i;
        int n = nb + ln;
        float invd = 1.f / fmaxf(g_deg[n], 1.f);
        float acc = g_agg[n * D + f] * invd + cb;
        g_agg[n * D + f] = 0.f;
#pragma unroll 8
        for (int d = 0; d < D; d++) acc += sh[ln][d] * sroot[d][f];
        sm[ln][f] = lrelu(acc);
    }
    __syncthreads();

    float gir[4], giz[4], gin[4], ghr[4], ghz[4], ghn[4];
    float bir = bih[f], biz = bih[D + f], bin = bih[2 * D + f];
    float bhr = bhh[f], bhz = bhh[D + f], bhn = bhh[2 * D + f];
#pragma unroll
    for (int i = 0; i < 4; i++) {
        gir[i] = bir; giz[i] = biz; gin[i] = bin;
        ghr[i] = bhr; ghz[i] = bhz; ghn[i] = bhn;
    }

#pragma unroll 4
    for (int k = 0; k < D; k++) {
        float4 wi = *(const float4*)&g_Wi4[(k * D + f) * 4];
        float4 wh = *(const float4*)&g_Wh4[(k * D + f) * 4];
#pragma unroll
        for (int i = 0; i < 4; i++) {
            int ln = ng + 4 * i;
            float mk = sm[ln][k];
            float hk = sh[ln][k];
            gir[i] += mk * wi.x; giz[i] += mk * wi.y; gin[i] += mk * wi.z;
            ghr[i] += hk * wh.x; ghz[i] += hk * wh.y; ghn[i] += hk * wh.z;
        }
    }

#pragma unroll
    for (int i = 0; i < 4; i++) {
        int ln = ng + 4 * i;
        float r  = sigm(gir[i] + ghr[i]);
        float z  = sigm(giz[i] + ghz[i]);
        float nn = tanhf(gin[i] + r * ghn[i]);
        float hv = (1.f - z) * nn + z * sh[ln][f];
        g_h[(nb + ln) * D + f] = hv;
        g_h_h[(nb + ln) * D + f] = __float2half(hv);
    }
}

// ---------------- set2set + head ----------------

__global__ void k_s2s_init(const float* __restrict__ lbih,
                           const float* __restrict__ lbhh) {
    int t = threadIdx.x;
    if (t < D) {
        float gi = lbih[t]         + lbhh[t];
        float gg = lbih[2 * D + t] + lbhh[2 * D + t];
        float go = lbih[3 * D + t] + lbhh[3 * D + t];
        float cl = sigm(gi) * tanhf(gg);
        g_q[t] = sigm(go) * tanhf(cl);
    }
    if (t < BG) { g_emax[t] = -3.4e38f; g_asum[t] = 0.f; }
    for (int i = t; i < BG * D; i += blockDim.x) g_rpool[i] = 0.f;
}

__global__ void k_dot(const int* __restrict__ batch) {
    int lane = threadIdx.x & 31;
    int warp = threadIdx.x >> 5;
    int n = blockIdx.x * 8 + warp;
    if (n >= N_NODES) return;
    float v = g_h[n * D + lane] * g_q[lane] + g_h[n * D + 32 + lane] * g_q[32 + lane];
#pragma unroll
    for (int o = 16; o > 0; o >>= 1) v += __shfl_down_sync(0xFFFFFFFFu, v, o);
    if (lane == 0) {
        g_e[n] = v;
        atomicMaxF(&g_emax[batch[n]], v);
    }
}

__global__ void k_exp(const int* __restrict__ batch) {
    int n = blockIdx.x * blockDim.x + threadIdx.x;
    if (n >= N_NODES) return;
    int g = batch[n];
    float a = expf(g_e[n] - g_emax[g]);
    g_a[n] = a;
    atomicAdd(&g_asum[g], a);
}

__global__ void k_pool(const int* __restrict__ batch) {
    int idx = blockIdx.x * blockDim.x + threadIdx.x;
    if (idx >= N_NODES * D) return;
    int n = idx >> 6, f = idx & 63;
    int g = batch[n];
    float w = g_a[n] / g_asum[g];
    atomicAdd(&g_rpool[g * D + f], w * g_h[idx]);
}

__global__ void k_out(const float* __restrict__ Wout,
                      const float* __restrict__ bout,
                      float* __restrict__ out) {
    int t = threadIdx.x;
    if (t >= BG * 2) return;
    int b = t >> 1, c = t & 1;
    float acc = bout[c];
#pragma unroll 8
    for (int j = 0; j < D; j++) {
        acc += g_q[j] * Wout[j * 2 + c];
        acc += g_rpool[b * D + j] * Wout[(D + j) * 2 + c];
    }
    out[b * 2 + c] = acc;
}

// ---------------- launch ----------------

extern "C" void kernel_launch(void* const* d_in, const int* in_sizes, int n_in,
                              void* d_out, int out_size) {
    const float* x      = (const float*)d_in[0];
    const float* ea     = (const float*)d_in[1];
    const int*   ei     = (const int*)d_in[2];
    const int*   batch  = (const int*)d_in[3];
    const float* W0     = (const float*)d_in[4];
    const float* b0     = (const float*)d_in[5];
    const float* We1    = (const float*)d_in[6];
    const float* be1    = (const float*)d_in[7];
    const float* We2    = (const float*)d_in[8];
    const float* be2    = (const float*)d_in[9];
    const float* root   = (const float*)d_in[10];
    const float* conv_b = (const float*)d_in[11];
    const float* Wih    = (const float*)d_in[12];
    const float* Whh    = (const float*)d_in[13];
    const float* bih    = (const float*)d_in[14];
    const float* bhh    = (const float*)d_in[15];
    const float* lbih   = (const float*)d_in[18];
    const float* lbhh   = (const float*)d_in[19];
    const float* Wout   = (const float*)d_in[20];
    const float* bout   = (const float*)d_in[21];
    float* out = (float*)d_out;
    (void)in_sizes; (void)n_in; (void)out_size;

    const int TGEMM_SMEM = (256 * 72 + 64 * 72 + 64 * 264) * (int)sizeof(__half); // 79872
    cudaFuncSetAttribute(k_t_gemm, cudaFuncAttributeMaxDynamicSharedMemorySize, TGEMM_SMEM);

    dim3 tgrid(17, N_NODES / 256);   // 272 blocks = 1 wave @ 2 blocks/SM

    // launch order: index 3 (ncu capture slot) = first k_t_gemm
    k_node_init<<<(N_NODES * D) / 256, 256>>>(x, W0, b0);           // 0
    k_edge_init<<<(N_EDGES * D) / 256, 256>>>(ea, We1, be1, ei);    // 1
    k_prep_we2rt<<<(TWPAD * D) / 256, 256>>>(We2, be2);             // 2
    k_t_gemm<<<tgrid, 512, TGEMM_SMEM>>>();                         // 3  <- profiled
    k_prep_gru<<<(D * D * 4) / 256, 256>>>(Wih, Whh);               // 4
    k_msg<<<N_EDGES / 16, 256>>>(ei);                               // 5
    k_node_update<<<N_NODES / 16, 256>>>(root, conv_b, bih, bhh);   // 6

    for (int it = 1; it < 6; it++) {
        k_t_gemm<<<tgrid, 512, TGEMM_SMEM>>>();
        k_msg<<<N_EDGES / 16, 256>>>(ei);
        k_node_update<<<N_NODES / 16, 256>>>(root, conv_b, bih, bhh);
    }

    k_s2s_init<<<1, 256>>>(lbih, lbhh);
    k_dot<<<N_NODES / 8, 256>>>(batch);
    k_exp<<<(N_NODES + 255) / 256, 256>>>(batch);
    k_pool<<<(N_NODES * D) / 256, 256>>>(batch);
    k_out<<<1, 64>>>(Wout, bout, out);
}